// round 13
// baseline (speedup 1.0000x reference)
#include <cuda_runtime.h>

// VPNNetwork fused (R13): R12 + swizzled weight layout (1-wavefront GEMM
// weight loads) + one-hot row add moved post-handoff (per-sample).
//   d_in[0] obs_flat [B,48] | d_in[1] Phi_w [48,48] | d_in[2] Phi_b [48]
//   d_in[3] Logit_w [4,36]  | d_in[4] Logit_b [4]   | out [B,4] f32

#define BT 128
#define ST 132          // element-major obs stride (floats)
#define PS 52           // sample-major phi row stride (floats)

typedef unsigned long long ull;
__device__ __forceinline__ ull dup2(float x) {
    ull d; asm("mov.b64 %0, {%1, %1};" : "=l"(d) : "f"(x)); return d;
}
__device__ __forceinline__ void upk(ull d, float& a, float& b) {
    asm("mov.b64 {%0, %1}, %2;" : "=f"(a), "=f"(b) : "l"(d));
}
__device__ __forceinline__ ull fma2(ull a, ull b, ull c) {
    ull d; asm("fma.rn.f32x2 %0, %1, %2, %3;" : "=l"(d) : "l"(a), "l"(b), "l"(c));
    return d;
}

__global__ __launch_bounds__(BT, 5) void vpn_kernel(
    const float* __restrict__ obs, const float* __restrict__ Pw,
    const float* __restrict__ Pb,  const float* __restrict__ Lw,
    const float* __restrict__ Lb,  float* __restrict__ out)
{
    // unified region: phase 1 = obs element-major [e<32][ST];
    // phase 2 = phi sample-major [s<128][PS]. 128*52 covers both.
    __shared__ __align__(16) float ar[128 * PS];
    // swizzled weights: wt2[e*48 + u*16 + ng*4 + q] = Pw[(12ng+4u+q)*48 + e]
    __shared__ __align__(16) float wt2[48 * 48];
    __shared__ __align__(16) float pb[48];
    __shared__ __align__(16) float lw[144];     // lw[k*4+a] = Lw[a*36+k]
    __shared__ __align__(16) float lb[4];
    __shared__ __align__(16) int spos[BT];

    const int tid = threadIdx.x;
    const int base = blockIdx.x * BT;

    // ---- weights into shared (coalesced read, swizzled scatter) ----
    for (int idx = tid; idx < 48 * 48; idx += BT) {
        int o = idx / 48, i = idx - o * 48;       // Pw[o][i]
        int ngs = o / 12, rem = o - ngs * 12;
        int u = rem >> 2, q = rem & 3;
        wt2[i * 48 + u * 16 + ngs * 4 + q] = Pw[idx];
    }
    if (tid < 48) pb[tid] = Pb[tid];
    for (int idx = tid; idx < 144; idx += BT) {
        int a = idx / 36, k = idx - a * 36;
        lw[k * 4 + a] = Lw[idx];
    }
    if (tid < 4) lb[tid] = Lb[tid];

    // ---- stage dense obs rows ar[(2c+(ch>>1))*ST + s]; pos detected inline ----
    const float4* g4 = reinterpret_cast<const float4*>(obs + (size_t)base * 48);
    #pragma unroll
    for (int k = 0; k < 12; k++) {
        int idx4 = tid + k * BT;
        float4 q = g4[idx4];
        int s = idx4 / 12, e0 = (idx4 - s * 12) * 4;
        float vv[4] = {q.x, q.y, q.z, q.w};
        #pragma unroll
        for (int j = 0; j < 4; j++) {
            int e = e0 + j, c = e / 3, ch = e - c * 3;
            if (ch == 1) { if (vv[j] != 0.0f) spos[s] = c; }
            else ar[(2 * c + (ch >> 1)) * ST + s] = vv[j];
        }
    }
    __syncthreads();

    // ---- Phi GEMM: 4 samples x 12 outputs/thread, f32x2 output-packed ----
    const int mg = tid >> 2, ng = tid & 3, ob = ng * 12;
    ull acc[4][6];
    {
        const ull* pb2 = reinterpret_cast<const ull*>(pb + ob);
        #pragma unroll
        for (int t = 0; t < 6; t++) {
            ull b = pb2[t];
            acc[0][t] = b; acc[1][t] = b; acc[2][t] = b; acc[3][t] = b;
        }
    }
    #pragma unroll
    for (int r = 0; r < 32; r++) {
        const int e = 3 * (r >> 1) + ((r & 1) << 1);    // input index, ch in {0,2}
        float4 xv = *reinterpret_cast<const float4*>(&ar[r * ST + 4 * mg]);
        const float* wbase = wt2 + e * 48 + ng * 4;     // 64B warp window per load
        ulonglong2 wa = *reinterpret_cast<const ulonglong2*>(wbase);       // u=0
        ulonglong2 wb = *reinterpret_cast<const ulonglong2*>(wbase + 16);  // u=1
        ulonglong2 wc = *reinterpret_cast<const ulonglong2*>(wbase + 32);  // u=2
        ull x[4] = {dup2(xv.x), dup2(xv.y), dup2(xv.z), dup2(xv.w)};
        #pragma unroll
        for (int j = 0; j < 4; j++) {
            acc[j][0] = fma2(x[j], wa.x, acc[j][0]);
            acc[j][1] = fma2(x[j], wa.y, acc[j][1]);
            acc[j][2] = fma2(x[j], wb.x, acc[j][2]);
            acc[j][3] = fma2(x[j], wb.y, acc[j][3]);
            acc[j][4] = fma2(x[j], wc.x, acc[j][4]);
            acc[j][5] = fma2(x[j], wc.y, acc[j][5]);
        }
    }
    float ph[4][12];
    #pragma unroll
    for (int j = 0; j < 4; j++)
        #pragma unroll
        for (int t = 0; t < 6; t++) upk(acc[j][t], ph[j][2 * t], ph[j][2 * t + 1]);

    // ---- obs part of logits (obs rows still alive; 1 thread = sample tid) ----
    const int mypos = spos[tid];
    const int phh = mypos >> 2, pww = mypos & 3;
    float4 w17 = *reinterpret_cast<const float4*>(lw + 17 * 4); // center ch1, val 1.0
    float lg0 = lb[0] + w17.x, lg1 = lb[1] + w17.y;
    float lg2 = lb[2] + w17.z, lg3 = lb[3] + w17.w;
    #pragma unroll
    for (int h = 0; h < 4; h++)
        #pragma unroll
        for (int w = 0; w < 4; w++) {
            const int c = h * 4 + w;
            int di = h - phh + 1, dj = w - pww + 1;
            if ((unsigned)di < 3u && (unsigned)dj < 3u) {
                int kb = (di * 3 + dj) * 4;
                float o0 = ar[(2 * c + 0) * ST + tid];
                float o2 = ar[(2 * c + 1) * ST + tid];
                float4 a0 = *reinterpret_cast<const float4*>(lw + (kb + 0) * 4);
                float4 a2 = *reinterpret_cast<const float4*>(lw + (kb + 2) * 4);
                lg0 = fmaf(o0, a0.x, lg0); lg1 = fmaf(o0, a0.y, lg1);
                lg2 = fmaf(o0, a0.z, lg2); lg3 = fmaf(o0, a0.w, lg3);
                lg0 = fmaf(o2, a2.x, lg0); lg1 = fmaf(o2, a2.y, lg1);
                lg2 = fmaf(o2, a2.z, lg2); lg3 = fmaf(o2, a2.w, lg3);
            }
        }

    // ---- overwrite ar with phi (no one-hot yet), SAMPLE-major ar[s*PS+o] ----
    __syncthreads();
    #pragma unroll
    for (int j = 0; j < 4; j++) {
        float* row = ar + (4 * mg + j) * PS + ob;
        *reinterpret_cast<float4*>(row + 0) =
            make_float4(ph[j][0], ph[j][1], ph[j][2], ph[j][3]);
        *reinterpret_cast<float4*>(row + 4) =
            make_float4(ph[j][4], ph[j][5], ph[j][6], ph[j][7]);
        *reinterpret_cast<float4*>(row + 8) =
            make_float4(ph[j][8], ph[j][9], ph[j][10], ph[j][11]);
    }
    __syncthreads();

    // ---- read own phi row (12 LDS.128), add one-hot row per-sample ----
    float phr[48];
    {
        const float4* row4 = reinterpret_cast<const float4*>(ar + tid * PS);
        #pragma unroll
        for (int u4 = 0; u4 < 12; u4++) {
            float4 q = row4[u4];
            phr[4 * u4 + 0] = q.x; phr[4 * u4 + 1] = q.y;
            phr[4 * u4 + 2] = q.z; phr[4 * u4 + 3] = q.w;
        }
    }
    // one-hot ch1 contribution: += Pw[:, 3*mypos+1] (value exactly 1.0).
    // wt2 row eh is contiguous; only 16 possible eh per warp -> broadcasts.
    {
        const int eh = 3 * mypos + 1;
        const float4* hrow = reinterpret_cast<const float4*>(wt2 + eh * 48);
        #pragma unroll
        for (int u = 0; u < 3; u++)
            #pragma unroll
            for (int g = 0; g < 4; g++) {
                float4 f = hrow[u * 4 + g];           // outputs 12g+4u+{0..3}
                int o = 12 * g + 4 * u;
                phr[o + 0] += f.x; phr[o + 1] += f.y;
                phr[o + 2] += f.z; phr[o + 3] += f.w;
            }
    }

    // ---- VI (register-resident) ----
    float rin[16], rout[16], p_[16], v_[16];
    #pragma unroll
    for (int c = 0; c < 16; c++) {
        rin[c]  = phr[3 * c + 0];
        rout[c] = phr[3 * c + 1];
        p_[c]   = phr[3 * c + 2];
        v_[c]   = 0.0f;
    }
    float rrU[16], rrD[16], rrL[16], rrR[16];
    #pragma unroll
    for (int h = 0; h < 4; h++)
        #pragma unroll
        for (int w = 0; w < 4; w++) {
            int c = h * 4 + w; float ro = rout[c];
            if (h > 0) rrU[c] = (rin[c - 4] != 0.0f) ? rin[c - 4] - ro : 0.0f;
            if (h < 3) rrD[c] = (rin[c + 4] != 0.0f) ? rin[c + 4] - ro : 0.0f;
            if (w > 0) rrL[c] = (rin[c - 1] != 0.0f) ? rin[c - 1] - ro : 0.0f;
            if (w < 3) rrR[c] = (rin[c + 1] != 0.0f) ? rin[c + 1] - ro : 0.0f;
        }
    #pragma unroll 4
    for (int k = 0; k < 20; k++) {
        float nv[16];
        #pragma unroll
        for (int h = 0; h < 4; h++)
            #pragma unroll
            for (int w = 0; w < 4; w++) {
                int c = h * 4 + w; float best = v_[c];
                if (h > 0) best = fmaxf(best, fmaf(p_[c], v_[c - 4], rrU[c]));
                if (h < 3) best = fmaxf(best, fmaf(p_[c], v_[c + 4], rrD[c]));
                if (w > 0) best = fmaxf(best, fmaf(p_[c], v_[c - 1], rrL[c]));
                if (w < 3) best = fmaxf(best, fmaf(p_[c], v_[c + 1], rrR[c]));
                nv[c] = best;
            }
        #pragma unroll
        for (int c = 0; c < 16; c++) v_[c] = nv[c];
    }

    // ---- v part of logits (values in registers) ----
    #pragma unroll
    for (int h = 0; h < 4; h++)
        #pragma unroll
        for (int w = 0; w < 4; w++) {
            const int c = h * 4 + w;
            int di = h - phh + 1, dj = w - pww + 1;
            if ((unsigned)di < 3u && (unsigned)dj < 3u) {
                int kb = (di * 3 + dj) * 4;
                float4 a3 = *reinterpret_cast<const float4*>(lw + (kb + 3) * 4);
                float vv = v_[c];
                lg0 = fmaf(vv, a3.x, lg0); lg1 = fmaf(vv, a3.y, lg1);
                lg2 = fmaf(vv, a3.z, lg2); lg3 = fmaf(vv, a3.w, lg3);
            }
        }

    reinterpret_cast<float4*>(out)[base + tid] = make_float4(lg0, lg1, lg2, lg3);
}

extern "C" void kernel_launch(void* const* d_in, const int* in_sizes, int n_in,
                              void* d_out, int out_size)
{
    const float* obs = (const float*)d_in[0];
    const float* Pw  = (const float*)d_in[1];
    const float* Pb  = (const float*)d_in[2];
    const float* Lw  = (const float*)d_in[3];
    const float* Lb  = (const float*)d_in[4];
    float* out = (float*)d_out;
    int B = in_sizes[0] / 48;                 // 262144
    vpn_kernel<<<B / BT, BT>>>(obs, Pw, Pb, Lw, Lb, out);
}

// round 14
// speedup vs baseline: 1.0322x; 1.0322x over previous
#include <cuda_runtime.h>

// VPNNetwork fused (R14): R12 + swizzled weight layout ONLY (controlled).
// wt2[e*48 + u*16 + ng*4 + q] = Pw[(12ng+4u+q)*48 + e] -> GEMM weight loads
// span 64B/warp (1 wavefront); one-hot add stays amortized in GEMM phase.
//   d_in[0] obs_flat [B,48] | d_in[1] Phi_w [48,48] | d_in[2] Phi_b [48]
//   d_in[3] Logit_w [4,36]  | d_in[4] Logit_b [4]   | out [B,4] f32

#define BT 128
#define ST 132          // element-major obs stride (floats)
#define PS 52           // sample-major phi row stride (floats)

typedef unsigned long long ull;
__device__ __forceinline__ ull dup2(float x) {
    ull d; asm("mov.b64 %0, {%1, %1};" : "=l"(d) : "f"(x)); return d;
}
__device__ __forceinline__ void upk(ull d, float& a, float& b) {
    asm("mov.b64 {%0, %1}, %2;" : "=f"(a), "=f"(b) : "l"(d));
}
__device__ __forceinline__ ull fma2(ull a, ull b, ull c) {
    ull d; asm("fma.rn.f32x2 %0, %1, %2, %3;" : "=l"(d) : "l"(a), "l"(b), "l"(c));
    return d;
}
__device__ __forceinline__ ull add2(ull a, ull b) {
    ull d; asm("add.rn.f32x2 %0, %1, %2;" : "=l"(d) : "l"(a), "l"(b)); return d;
}

__global__ __launch_bounds__(BT, 5) void vpn_kernel(
    const float* __restrict__ obs, const float* __restrict__ Pw,
    const float* __restrict__ Pb,  const float* __restrict__ Lw,
    const float* __restrict__ Lb,  float* __restrict__ out)
{
    // unified region: phase 1 = obs element-major [e<32][ST];
    // phase 2 = phi sample-major [s<128][PS]. 128*52 covers both.
    __shared__ __align__(16) float ar[128 * PS];
    __shared__ __align__(16) float wt2[48 * 48];   // swizzled weights
    __shared__ __align__(16) float pb[48];
    __shared__ __align__(16) float lw[144];        // lw[k*4+a] = Lw[a*36+k]
    __shared__ __align__(16) float lb[4];
    __shared__ __align__(16) int spos[BT];

    const int tid = threadIdx.x;
    const int base = blockIdx.x * BT;

    // ---- weights into shared (coalesced read, swizzled scatter) ----
    for (int idx = tid; idx < 48 * 48; idx += BT) {
        int o = idx / 48, i = idx - o * 48;        // Pw[o][i]
        int ngs = o / 12, rem = o - ngs * 12;
        int u = rem >> 2, q = rem & 3;
        wt2[i * 48 + u * 16 + ngs * 4 + q] = Pw[idx];
    }
    if (tid < 48) pb[tid] = Pb[tid];
    for (int idx = tid; idx < 144; idx += BT) {
        int a = idx / 36, k = idx - a * 36;
        lw[k * 4 + a] = Lw[idx];
    }
    if (tid < 4) lb[tid] = Lb[tid];

    // ---- stage dense obs rows ar[(2c+(ch>>1))*ST + s]; pos detected inline ----
    const float4* g4 = reinterpret_cast<const float4*>(obs + (size_t)base * 48);
    #pragma unroll
    for (int k = 0; k < 12; k++) {
        int idx4 = tid + k * BT;
        float4 q = g4[idx4];
        int s = idx4 / 12, e0 = (idx4 - s * 12) * 4;
        float vv[4] = {q.x, q.y, q.z, q.w};
        #pragma unroll
        for (int j = 0; j < 4; j++) {
            int e = e0 + j, c = e / 3, ch = e - c * 3;
            if (ch == 1) { if (vv[j] != 0.0f) spos[s] = c; }
            else ar[(2 * c + (ch >> 1)) * ST + s] = vv[j];
        }
    }
    __syncthreads();

    // ---- Phi GEMM: 4 samples x 12 outputs/thread, f32x2 output-packed ----
    const int mg = tid >> 2, ng = tid & 3, ob = ng * 12;
    ull acc[4][6];
    {
        const ull* pb2 = reinterpret_cast<const ull*>(pb + ob);
        #pragma unroll
        for (int t = 0; t < 6; t++) {
            ull b = pb2[t];
            acc[0][t] = b; acc[1][t] = b; acc[2][t] = b; acc[3][t] = b;
        }
    }
    #pragma unroll
    for (int r = 0; r < 32; r++) {
        const int e = 3 * (r >> 1) + ((r & 1) << 1);    // input index, ch in {0,2}
        float4 xv = *reinterpret_cast<const float4*>(&ar[r * ST + 4 * mg]);
        const float* wbase = wt2 + e * 48 + ng * 4;     // 64B warp window per load
        ulonglong2 wa = *reinterpret_cast<const ulonglong2*>(wbase);       // o=ob+0..3
        ulonglong2 wb = *reinterpret_cast<const ulonglong2*>(wbase + 16);  // o=ob+4..7
        ulonglong2 wc = *reinterpret_cast<const ulonglong2*>(wbase + 32);  // o=ob+8..11
        ull x[4] = {dup2(xv.x), dup2(xv.y), dup2(xv.z), dup2(xv.w)};
        #pragma unroll
        for (int j = 0; j < 4; j++) {
            acc[j][0] = fma2(x[j], wa.x, acc[j][0]);
            acc[j][1] = fma2(x[j], wa.y, acc[j][1]);
            acc[j][2] = fma2(x[j], wb.x, acc[j][2]);
            acc[j][3] = fma2(x[j], wb.y, acc[j][3]);
            acc[j][4] = fma2(x[j], wc.x, acc[j][4]);
            acc[j][5] = fma2(x[j], wc.y, acc[j][5]);
        }
    }
    // one-hot ch1: += Pw[:,3*pos+1] slice (value exactly 1.0), amortized 4-way
    {
        int4 p4 = reinterpret_cast<const int4*>(spos)[mg];
        int pj[4] = {p4.x, p4.y, p4.z, p4.w};
        #pragma unroll
        for (int j = 0; j < 4; j++) {
            const float* hbase = wt2 + (3 * pj[j] + 1) * 48 + ng * 4;
            ulonglong2 ha = *reinterpret_cast<const ulonglong2*>(hbase);
            ulonglong2 hb = *reinterpret_cast<const ulonglong2*>(hbase + 16);
            ulonglong2 hc = *reinterpret_cast<const ulonglong2*>(hbase + 32);
            acc[j][0] = add2(acc[j][0], ha.x); acc[j][1] = add2(acc[j][1], ha.y);
            acc[j][2] = add2(acc[j][2], hb.x); acc[j][3] = add2(acc[j][3], hb.y);
            acc[j][4] = add2(acc[j][4], hc.x); acc[j][5] = add2(acc[j][5], hc.y);
        }
    }
    float ph[4][12];
    #pragma unroll
    for (int j = 0; j < 4; j++)
        #pragma unroll
        for (int t = 0; t < 6; t++) upk(acc[j][t], ph[j][2 * t], ph[j][2 * t + 1]);

    // ---- obs part of logits (obs rows still alive; 1 thread = sample tid) ----
    const int mypos = spos[tid];
    const int phh = mypos >> 2, pww = mypos & 3;
    float4 w17 = *reinterpret_cast<const float4*>(lw + 17 * 4); // center ch1, val 1.0
    float lg0 = lb[0] + w17.x, lg1 = lb[1] + w17.y;
    float lg2 = lb[2] + w17.z, lg3 = lb[3] + w17.w;
    #pragma unroll
    for (int h = 0; h < 4; h++)
        #pragma unroll
        for (int w = 0; w < 4; w++) {
            const int c = h * 4 + w;
            int di = h - phh + 1, dj = w - pww + 1;
            if ((unsigned)di < 3u && (unsigned)dj < 3u) {
                int kb = (di * 3 + dj) * 4;
                float o0 = ar[(2 * c + 0) * ST + tid];
                float o2 = ar[(2 * c + 1) * ST + tid];
                float4 a0 = *reinterpret_cast<const float4*>(lw + (kb + 0) * 4);
                float4 a2 = *reinterpret_cast<const float4*>(lw + (kb + 2) * 4);
                lg0 = fmaf(o0, a0.x, lg0); lg1 = fmaf(o0, a0.y, lg1);
                lg2 = fmaf(o0, a0.z, lg2); lg3 = fmaf(o0, a0.w, lg3);
                lg0 = fmaf(o2, a2.x, lg0); lg1 = fmaf(o2, a2.y, lg1);
                lg2 = fmaf(o2, a2.z, lg2); lg3 = fmaf(o2, a2.w, lg3);
            }
        }

    // ---- overwrite ar with phi, SAMPLE-major: ar[s*PS + o] ----
    __syncthreads();
    #pragma unroll
    for (int j = 0; j < 4; j++) {
        float* row = ar + (4 * mg + j) * PS + ob;
        *reinterpret_cast<float4*>(row + 0) =
            make_float4(ph[j][0], ph[j][1], ph[j][2], ph[j][3]);
        *reinterpret_cast<float4*>(row + 4) =
            make_float4(ph[j][4], ph[j][5], ph[j][6], ph[j][7]);
        *reinterpret_cast<float4*>(row + 8) =
            make_float4(ph[j][8], ph[j][9], ph[j][10], ph[j][11]);
    }
    __syncthreads();

    // ---- VI: read own phi row with 12 LDS.128 ----
    float phr[48];
    {
        const float4* row4 = reinterpret_cast<const float4*>(ar + tid * PS);
        #pragma unroll
        for (int u4 = 0; u4 < 12; u4++) {
            float4 q = row4[u4];
            phr[4 * u4 + 0] = q.x; phr[4 * u4 + 1] = q.y;
            phr[4 * u4 + 2] = q.z; phr[4 * u4 + 3] = q.w;
        }
    }
    float rin[16], rout[16], p_[16], v_[16];
    #pragma unroll
    for (int c = 0; c < 16; c++) {
        rin[c]  = phr[3 * c + 0];
        rout[c] = phr[3 * c + 1];
        p_[c]   = phr[3 * c + 2];
        v_[c]   = 0.0f;
    }
    float rrU[16], rrD[16], rrL[16], rrR[16];
    #pragma unroll
    for (int h = 0; h < 4; h++)
        #pragma unroll
        for (int w = 0; w < 4; w++) {
            int c = h * 4 + w; float ro = rout[c];
            if (h > 0) rrU[c] = (rin[c - 4] != 0.0f) ? rin[c - 4] - ro : 0.0f;
            if (h < 3) rrD[c] = (rin[c + 4] != 0.0f) ? rin[c + 4] - ro : 0.0f;
            if (w > 0) rrL[c] = (rin[c - 1] != 0.0f) ? rin[c - 1] - ro : 0.0f;
            if (w < 3) rrR[c] = (rin[c + 1] != 0.0f) ? rin[c + 1] - ro : 0.0f;
        }
    #pragma unroll 4
    for (int k = 0; k < 20; k++) {
        float nv[16];
        #pragma unroll
        for (int h = 0; h < 4; h++)
            #pragma unroll
            for (int w = 0; w < 4; w++) {
                int c = h * 4 + w; float best = v_[c];
                if (h > 0) best = fmaxf(best, fmaf(p_[c], v_[c - 4], rrU[c]));
                if (h < 3) best = fmaxf(best, fmaf(p_[c], v_[c + 4], rrD[c]));
                if (w > 0) best = fmaxf(best, fmaf(p_[c], v_[c - 1], rrL[c]));
                if (w < 3) best = fmaxf(best, fmaf(p_[c], v_[c + 1], rrR[c]));
                nv[c] = best;
            }
        #pragma unroll
        for (int c = 0; c < 16; c++) v_[c] = nv[c];
    }

    // ---- v part of logits (values in registers) ----
    #pragma unroll
    for (int h = 0; h < 4; h++)
        #pragma unroll
        for (int w = 0; w < 4; w++) {
            const int c = h * 4 + w;
            int di = h - phh + 1, dj = w - pww + 1;
            if ((unsigned)di < 3u && (unsigned)dj < 3u) {
                int kb = (di * 3 + dj) * 4;
                float4 a3 = *reinterpret_cast<const float4*>(lw + (kb + 3) * 4);
                float vv = v_[c];
                lg0 = fmaf(vv, a3.x, lg0); lg1 = fmaf(vv, a3.y, lg1);
                lg2 = fmaf(vv, a3.z, lg2); lg3 = fmaf(vv, a3.w, lg3);
            }
        }

    reinterpret_cast<float4*>(out)[base + tid] = make_float4(lg0, lg1, lg2, lg3);
}

extern "C" void kernel_launch(void* const* d_in, const int* in_sizes, int n_in,
                              void* d_out, int out_size)
{
    const float* obs = (const float*)d_in[0];
    const float* Pw  = (const float*)d_in[1];
    const float* Pb  = (const float*)d_in[2];
    const float* Lw  = (const float*)d_in[3];
    const float* Lb  = (const float*)d_in[4];
    float* out = (float*)d_out;
    int B = in_sizes[0] / 48;                 // 262144
    vpn_kernel<<<B / BT, BT>>>(obs, Pw, Pb, Lw, Lb, out);
}